// round 13
// baseline (speedup 1.0000x reference)
#include <cuda_runtime.h>
#include <cuda_fp16.h>
#include <math.h>
#include <stdint.h>

#define B_   64
#define L_   1024
#define ENC_ 2048
#define DEC_ 512
#define ATT_ 512
#define BL_  (B_ * L_)

// ---------------------------------------------------------------------------
// Device scratch
// ---------------------------------------------------------------------------
__device__ float g_H[B_ * ATT_];                          // proj_h + b2 + b1
// W1 fp16, layout [c=k/32][n 512][k 32]
__device__ __align__(128) __half g_B16[ENC_ * ATT_];
__device__ float g_scorep[4 * BL_];                       // per-N-chunk score partials
__device__ float g_ctxp[8 * B_ * ENC_];                   // context partials

// ---------------------------------------------------------------------------
// Helpers
// ---------------------------------------------------------------------------
__device__ __forceinline__ uint32_t smem_u32(const void* p) {
    uint32_t a;
    asm("{ .reg .u64 t; cvta.to.shared.u64 t, %1; cvt.u32.u64 %0, t; }" : "=r"(a) : "l"(p));
    return a;
}
__device__ __forceinline__ void cp16(uint32_t dst, const void* src) {
    asm volatile("cp.async.cg.shared.global [%0], [%1], 16;" :: "r"(dst), "l"(src));
}
__device__ __forceinline__ void cp_commit() {
    asm volatile("cp.async.commit_group;" ::: "memory");
}
__device__ __forceinline__ void cp_wait0() {
    asm volatile("cp.async.wait_group 0;" ::: "memory");
}
__device__ __forceinline__ void ldsm_x4(uint32_t* r, uint32_t addr) {
    asm volatile("ldmatrix.sync.aligned.m8n8.x4.shared.b16 {%0,%1,%2,%3}, [%4];"
                 : "=r"(r[0]), "=r"(r[1]), "=r"(r[2]), "=r"(r[3]) : "r"(addr));
}
__device__ __forceinline__ void mma_f16(float* d, const uint32_t* a, const uint32_t* b) {
    asm volatile(
        "mma.sync.aligned.m16n8k16.row.col.f32.f16.f16.f32 "
        "{%0,%1,%2,%3}, {%4,%5,%6,%7}, {%8,%9}, {%0,%1,%2,%3};"
        : "+f"(d[0]), "+f"(d[1]), "+f"(d[2]), "+f"(d[3])
        : "r"(a[0]), "r"(a[1]), "r"(a[2]), "r"(a[3]), "r"(b[0]), "r"(b[1]));
}
__device__ __forceinline__ float fast_tanh(float x) {
    float e = __expf(2.f * x);
    return __fdividef(e - 1.f, e + 1.f);
}

// ---------------------------------------------------------------------------
// Kernel A: H = hidden @ W2 + b2 + b1
// ---------------------------------------------------------------------------
__global__ void proj_h_kernel(const float* __restrict__ hidden,
                              const float* __restrict__ W2,
                              const float* __restrict__ b2,
                              const float* __restrict__ b1) {
    __shared__ float hs[DEC_];
    int b = blockIdx.x, a = threadIdx.x;
    hs[a] = hidden[b * DEC_ + a];
    __syncthreads();
    float acc = 0.f;
#pragma unroll 8
    for (int d = 0; d < DEC_; ++d) acc += hs[d] * W2[d * ATT_ + a];
    g_H[b * ATT_ + a] = acc + b2[a] + b1[a];
}

// ---------------------------------------------------------------------------
// Kernel B: W1 [ENC, ATT] fp32 -> fp16, layout [c=k/32][n][k32]
// ---------------------------------------------------------------------------
__global__ void prep_B_kernel(const float* __restrict__ W1) {
    int idx = blockIdx.x * 256 + threadIdx.x;   // idx = k*512 + n
    if (idx >= ENC_ * ATT_) return;
    int k = idx >> 9, n = idx & 511;
    int c = k >> 5, kk = k & 31;
    g_B16[((size_t)(c * 512 + n) << 5) + kk] = __float2half_rn(W1[idx]);
}

// ---------------------------------------------------------------------------
// Kernel C: fused fp16 mma.sync GEMM + tanh + V-reduction -> score partials
// Grid: (4 nc, 512 m) nc-major. CTA: 128x128, 256 thr, KC=32, 2 stages.
// A: fp32 LDG->regs (prefetch) -> cvt fp16 -> STS, bulk per chunk, overlapped
//    with previous chunk's MMAs (R6 pipeline). No prep_F kernel.
// B: fp16 cp.async + paired ldsm (R8 path). 2 CTAs/SM.
// ---------------------------------------------------------------------------
static constexpr int PITCH  = 80;             // 64B fp16 data + 16B pad
static constexpr int TILE   = 128 * PITCH;    // 10240
static constexpr int STAGE  = 2 * TILE;       // A + B = 20480
static constexpr int OFF_A  = 0;
static constexpr int OFF_B  = TILE;
static constexpr int OFF_PART = 2 * STAGE;            // 40960
static constexpr int OFF_H    = OFF_PART + 1024;
static constexpr int OFF_V    = OFF_H + 512;
static constexpr int SMEM_TOTAL = OFF_V + 512;        // 43008
static constexpr int NCHUNK = ENC_ / 32;              // 64

__global__ __launch_bounds__(256, 2) void score_mma_kernel(
    const float* __restrict__ F, const float* __restrict__ V)
{
    extern __shared__ char smem[];
    const uint32_t sb = smem_u32(smem);
    const int tid  = threadIdx.x;
    const int lane = tid & 31;
    const int wid  = tid >> 5;
    const int wm   = wid & 3;        // warp m: 4 x 32 rows
    const int wn   = wid >> 2;       // warp n: 2 x 64 cols
    const int nc   = blockIdx.x;     // n chunk (128 cols)
    const int mb   = blockIdx.y;
    const int m0   = mb * 128;
    const int b    = mb >> 3;

    float* partS = (float*)(smem + OFF_PART);
    float* Hs    = (float*)(smem + OFF_H);
    float* Vs    = (float*)(smem + OFF_V);
    if (tid < 128) {
        Hs[tid] = g_H[b * ATT_ + nc * 128 + tid];
        Vs[tid] = V[nc * 128 + tid];
    }

    float d[2][8][4];
#pragma unroll
    for (int mt = 0; mt < 2; ++mt)
#pragma unroll
        for (int nt = 0; nt < 8; ++nt)
#pragma unroll
            for (int e = 0; e < 4; ++e) d[mt][nt][e] = 0.f;

    // A: 1024 float4 per chunk -> 4/thread: v = tid + t*256, row=v>>3, q=v&7
    const float* pF[4];
    uint32_t aDst[4];
#pragma unroll
    for (int t = 0; t < 4; ++t) {
        int v = tid + t * 256, row = v >> 3, q = v & 7;
        pF[t]   = F + (size_t)(m0 + row) * ENC_ + q * 4;
        aDst[t] = (uint32_t)(OFF_A + row * PITCH + q * 8);
    }
    // B: 512 x 16B units per chunk -> 2/thread
    const __half* pB[2];
    uint32_t bDst[2];
#pragma unroll
    for (int e = 0; e < 2; ++e) {
        int j = tid + e * 256, row = j >> 2, q = j & 3;
        pB[e]   = g_B16 + (((size_t)(nc * 128 + row)) << 5) + q * 8;
        bDst[e] = (uint32_t)(OFF_B + row * PITCH + q * 16);
    }

    // ---- prologue: chunk 0 -> stage 0 ----
    float4 fr[4];
#pragma unroll
    for (int t = 0; t < 4; ++t) { fr[t] = *(const float4*)pF[t]; pF[t] += 32; }
#pragma unroll
    for (int e = 0; e < 2; ++e) { cp16(sb + bDst[e], pB[e]); pB[e] += 512 * 32; }
    cp_commit();
#pragma unroll
    for (int t = 0; t < 4; ++t) {
        __half2 h01 = __floats2half2_rn(fr[t].x, fr[t].y);
        __half2 h23 = __floats2half2_rn(fr[t].z, fr[t].w);
        *(uint2*)(smem + aDst[t]) = make_uint2(*(uint32_t*)&h01, *(uint32_t*)&h23);
    }

    // ldsm base offsets (stage-relative)
    const uint32_t aoff0 = OFF_A + (uint32_t)(wm * 32 + (lane & 15)) * PITCH +
                           (uint32_t)(((lane >> 4) & 1) * 16);
    const uint32_t aoff1 = aoff0 + 16 * PITCH;
    uint32_t boff[4];
#pragma unroll
    for (int p = 0; p < 4; ++p)
        boff[p] = OFF_B + (uint32_t)(wn * 64 + p * 16 + (lane & 15)) * PITCH +
                  (uint32_t)(((lane >> 4) & 1) * 16);

#pragma unroll 1
    for (int i = 0; i < NCHUNK; ++i) {
        const int s = i & 1;
        const uint32_t stg = sb + s * STAGE;

        // prefetch A(i+1) fp32 into regs (overlaps wait + compute below)
        if (i + 1 < NCHUNK) {
#pragma unroll
            for (int t = 0; t < 4; ++t) { fr[t] = *(const float4*)pF[t]; pF[t] += 32; }
        }

        cp_wait0();
        __syncthreads();   // stage s populated; all warps done reading s^1

        if (i + 1 < NCHUNK) {
            const uint32_t nstg = sb + (s ^ 1) * STAGE;
#pragma unroll
            for (int e = 0; e < 2; ++e) { cp16(nstg + bDst[e], pB[e]); pB[e] += 512 * 32; }
            cp_commit();
#pragma unroll
            for (int t = 0; t < 4; ++t) {
                __half2 h01 = __floats2half2_rn(fr[t].x, fr[t].y);
                __half2 h23 = __floats2half2_rn(fr[t].z, fr[t].w);
                *(uint2*)((char*)smem + (s ^ 1) * STAGE + aDst[t]) =
                    make_uint2(*(uint32_t*)&h01, *(uint32_t*)&h23);
            }
        }

        // ---- compute chunk i on stage s: 2 k16 slabs (R8 path) ----
#pragma unroll
        for (int kk = 0; kk < 2; ++kk) {
            const uint32_t ko = (uint32_t)(kk * 32);
            uint32_t a0[4], a1[4];
            ldsm_x4(a0, stg + aoff0 + ko);
            ldsm_x4(a1, stg + aoff1 + ko);
            uint32_t bb[8][2];
#pragma unroll
            for (int p = 0; p < 4; ++p) {       // paired ldsm: 2 n-tiles per x4
                uint32_t r[4];
                ldsm_x4(r, stg + boff[p] + ko);
                bb[2 * p][0]     = r[0];
                bb[2 * p + 1][0] = r[1];
                bb[2 * p][1]     = r[2];
                bb[2 * p + 1][1] = r[3];
            }
#pragma unroll
            for (int nt = 0; nt < 8; ++nt) {
                mma_f16(d[0][nt], a0, bb[nt]);
                mma_f16(d[1][nt], a1, bb[nt]);
            }
        }
    }

    // ---- epilogue: tanh + V-weighted row reduction over this 128-col chunk ----
#pragma unroll
    for (int mt = 0; mt < 2; ++mt) {
        float s0 = 0.f, s1 = 0.f;
#pragma unroll
        for (int nt = 0; nt < 8; ++nt) {
            int c0 = wn * 64 + nt * 8 + (lane & 3) * 2;
            float h0 = Hs[c0], v0 = Vs[c0];
            float h1 = Hs[c0 + 1], v1 = Vs[c0 + 1];
            s0 += fast_tanh(d[mt][nt][0] + h0) * v0 + fast_tanh(d[mt][nt][1] + h1) * v1;
            s1 += fast_tanh(d[mt][nt][2] + h0) * v0 + fast_tanh(d[mt][nt][3] + h1) * v1;
        }
#pragma unroll
        for (int o = 1; o <= 2; o <<= 1) {
            s0 += __shfl_xor_sync(~0u, s0, o);
            s1 += __shfl_xor_sync(~0u, s1, o);
        }
        if ((lane & 3) == 0) {
            int r = wm * 32 + mt * 16 + (lane >> 2);
            partS[wn * 128 + r]     = s0;
            partS[wn * 128 + r + 8] = s1;
        }
    }
    __syncthreads();
    if (tid < 128)
        g_scorep[nc * BL_ + m0 + tid] = partS[tid] + partS[128 + tid];
}

// ---------------------------------------------------------------------------
// Kernel D: combine partials + softmax over L per batch
// ---------------------------------------------------------------------------
__global__ void softmax_kernel(const float* __restrict__ bv, float* __restrict__ w) {
    __shared__ float redm[32];
    __shared__ float reds[32];
    const int b = blockIdx.x, t = threadIdx.x;
    const int idx = b * L_ + t;
    float s = g_scorep[idx] + g_scorep[BL_ + idx] + g_scorep[2 * BL_ + idx] +
              g_scorep[3 * BL_ + idx] + bv[0];
    float m = s;
#pragma unroll
    for (int o = 16; o > 0; o >>= 1) m = fmaxf(m, __shfl_xor_sync(~0u, m, o));
    if ((t & 31) == 0) redm[t >> 5] = m;
    __syncthreads();
    if (t < 32) {
        float v = redm[t];
#pragma unroll
        for (int o = 16; o > 0; o >>= 1) v = fmaxf(v, __shfl_xor_sync(~0u, v, o));
        redm[t] = v;
    }
    __syncthreads();
    m = redm[0];
    const float e = expf(s - m);
    float sum = e;
#pragma unroll
    for (int o = 16; o > 0; o >>= 1) sum += __shfl_xor_sync(~0u, sum, o);
    if ((t & 31) == 0) reds[t >> 5] = sum;
    __syncthreads();
    if (t < 32) {
        float v = reds[t];
#pragma unroll
        for (int o = 16; o > 0; o >>= 1) v += __shfl_xor_sync(~0u, v, o);
        reds[t] = v;
    }
    __syncthreads();
    w[idx] = e / reds[0];
}

// ---------------------------------------------------------------------------
// Kernel E/F: context = sum_l w*F  (fp32 F; 8 L-partials, then reduced)
// ---------------------------------------------------------------------------
__global__ void context_part_kernel(const float* __restrict__ F,
                                    const float* __restrict__ w) {
    __shared__ float ws[128];
    const int b = blockIdx.y, z = blockIdx.z, t = threadIdx.x;
    const int l0 = z * 128;
    ws[t] = w[b * L_ + l0 + t];
    __syncthreads();
    const int e0 = blockIdx.x * 512 + t * 4;
    const float* fb = F + (size_t)b * L_ * ENC_ + (size_t)l0 * ENC_ + e0;
    float4 acc = make_float4(0.f, 0.f, 0.f, 0.f);
#pragma unroll 4
    for (int l = 0; l < 128; ++l) {
        float4 f = *(const float4*)(fb + (size_t)l * ENC_);
        const float wl = ws[l];
        acc.x += wl * f.x; acc.y += wl * f.y; acc.z += wl * f.z; acc.w += wl * f.w;
    }
    *(float4*)&g_ctxp[(size_t)(z * B_ + b) * ENC_ + e0] = acc;
}

__global__ void context_reduce_kernel(float* __restrict__ ctx) {
    const int i = (blockIdx.x * 256 + threadIdx.x) * 4;
    float4 acc = make_float4(0.f, 0.f, 0.f, 0.f);
#pragma unroll
    for (int p = 0; p < 8; ++p) {
        float4 a = *(const float4*)&g_ctxp[(size_t)p * B_ * ENC_ + i];
        acc.x += a.x; acc.y += a.y; acc.z += a.z; acc.w += a.w;
    }
    *(float4*)&ctx[i] = acc;
}

// ---------------------------------------------------------------------------
// Launch
// ---------------------------------------------------------------------------
extern "C" void kernel_launch(void* const* d_in, const int* in_sizes, int n_in,
                              void* d_out, int out_size) {
    const float* F   = (const float*)d_in[0];
    const float* hid = (const float*)d_in[1];
    const float* W1  = (const float*)d_in[2];
    const float* b1  = (const float*)d_in[3];
    const float* W2  = (const float*)d_in[4];
    const float* b2  = (const float*)d_in[5];
    const float* V   = (const float*)d_in[6];
    const float* bv  = (const float*)d_in[7];

    float* out = (float*)d_out;
    float* ctx = out;
    float* wts = out + B_ * ENC_;

    cudaFuncSetAttribute(score_mma_kernel,
                         cudaFuncAttributeMaxDynamicSharedMemorySize, SMEM_TOTAL);

    proj_h_kernel<<<B_, ATT_>>>(hid, W2, b2, b1);
    prep_B_kernel<<<(ENC_ * ATT_) / 256, 256>>>(W1);
    score_mma_kernel<<<dim3(4, BL_ / 128), 256, SMEM_TOTAL>>>(F, V);
    softmax_kernel<<<B_, L_>>>(bv, wts);
    context_part_kernel<<<dim3(ENC_ / 512, B_, 8), 128>>>(F, wts);
    context_reduce_kernel<<<(B_ * ENC_) / 1024, 256>>>(ctx);
}

// round 14
// speedup vs baseline: 1.0211x; 1.0211x over previous
#include <cuda_runtime.h>
#include <cuda_fp16.h>
#include <math.h>
#include <stdint.h>

#define B_   64
#define L_   1024
#define ENC_ 2048
#define DEC_ 512
#define ATT_ 512
#define BL_  (B_ * L_)

// ---------------------------------------------------------------------------
// Device scratch
// ---------------------------------------------------------------------------
__device__ float g_H[B_ * ATT_];                          // proj_h + b2 + b1
// W1 fp16, layout [c=k/64][n 512][k 64]
__device__ __align__(128) __half g_B16[ENC_ * ATT_];
// F fp16, layout [mb=row/128][c=k/64][row 128][k 64]
__device__ __align__(128) __half g_F16[(size_t)BL_ * ENC_];
__device__ float g_scorep[4 * BL_];                       // per-N-chunk score partials
__device__ float g_ctxp[8 * B_ * ENC_];                   // context partials

// ---------------------------------------------------------------------------
// Helpers
// ---------------------------------------------------------------------------
__device__ __forceinline__ uint32_t smem_u32(const void* p) {
    uint32_t a;
    asm("{ .reg .u64 t; cvta.to.shared.u64 t, %1; cvt.u32.u64 %0, t; }" : "=r"(a) : "l"(p));
    return a;
}
__device__ __forceinline__ void cp16(uint32_t dst, const void* src) {
    asm volatile("cp.async.cg.shared.global [%0], [%1], 16;" :: "r"(dst), "l"(src));
}
__device__ __forceinline__ void cp_commit() {
    asm volatile("cp.async.commit_group;" ::: "memory");
}
__device__ __forceinline__ void cp_wait1() {
    asm volatile("cp.async.wait_group 1;" ::: "memory");
}
__device__ __forceinline__ void ldsm_x4(uint32_t* r, uint32_t addr) {
    asm volatile("ldmatrix.sync.aligned.m8n8.x4.shared.b16 {%0,%1,%2,%3}, [%4];"
                 : "=r"(r[0]), "=r"(r[1]), "=r"(r[2]), "=r"(r[3]) : "r"(addr));
}
__device__ __forceinline__ void mma_f16(float* d, const uint32_t* a, const uint32_t* b) {
    asm volatile(
        "mma.sync.aligned.m16n8k16.row.col.f32.f16.f16.f32 "
        "{%0,%1,%2,%3}, {%4,%5,%6,%7}, {%8,%9}, {%0,%1,%2,%3};"
        : "+f"(d[0]), "+f"(d[1]), "+f"(d[2]), "+f"(d[3])
        : "r"(a[0]), "r"(a[1]), "r"(a[2]), "r"(a[3]), "r"(b[0]), "r"(b[1]));
}
__device__ __forceinline__ float fast_tanh(float x) {
    float e = __expf(2.f * x);
    return __fdividef(e - 1.f, e + 1.f);
}

// ---------------------------------------------------------------------------
// Kernel A: H = hidden @ W2 + b2 + b1
// ---------------------------------------------------------------------------
__global__ void proj_h_kernel(const float* __restrict__ hidden,
                              const float* __restrict__ W2,
                              const float* __restrict__ b2,
                              const float* __restrict__ b1) {
    __shared__ float hs[DEC_];
    int b = blockIdx.x, a = threadIdx.x;
    hs[a] = hidden[b * DEC_ + a];
    __syncthreads();
    float acc = 0.f;
#pragma unroll 8
    for (int d = 0; d < DEC_; ++d) acc += hs[d] * W2[d * ATT_ + a];
    g_H[b * ATT_ + a] = acc + b2[a] + b1[a];
}

// ---------------------------------------------------------------------------
// Kernel B1: W1 [ENC, ATT] fp32 -> fp16, layout [c][n][k64]
// ---------------------------------------------------------------------------
__global__ void prep_B_kernel(const float* __restrict__ W1) {
    int idx = blockIdx.x * 256 + threadIdx.x;   // idx = k*512 + n
    if (idx >= ENC_ * ATT_) return;
    int k = idx >> 9, n = idx & 511;
    int c = k >> 6, kk = k & 63;
    g_B16[((size_t)(c * 512 + n) << 6) + kk] = __float2half_rn(W1[idx]);
}

// ---------------------------------------------------------------------------
// Kernel B2: F [rows mb0*128 ...] fp32 -> fp16, layout [mb][c][row][k64]
// Launched per mb-quarter so it can overlap with score of earlier quarters.
// ---------------------------------------------------------------------------
__global__ void prep_F_kernel(const float* __restrict__ F, int mb0) {
    size_t f4 = (size_t)blockIdx.x * 256 + threadIdx.x +
                (size_t)mb0 * 128 * (ENC_ / 4);          // global float4 index
    size_t r  = f4 >> 9;            // global row (512 float4 per row)
    int   k   = (int)(f4 & 511) * 4;
    int   mb  = (int)(r >> 7), row = (int)(r & 127);
    int   c   = k >> 6, kk = k & 63;
    float4 f = *(const float4*)(F + (r << 11) + k);
    __half2 h01 = __floats2half2_rn(f.x, f.y);
    __half2 h23 = __floats2half2_rn(f.z, f.w);
    size_t o = (((size_t)(mb * 32 + c) * 128 + row) << 6) + kk;
    *(uint2*)(g_F16 + o) = make_uint2(*(uint32_t*)&h01, *(uint32_t*)&h23);
}

// ---------------------------------------------------------------------------
// Kernel C: fused fp16 mma.sync GEMM + tanh + V-reduction -> score partials
// Grid: (4 nc, 128 mb) per quarter, nc-major. CTA: 128x128, 256 thr, KC=64.
// 3-stage cp.async pipeline (wait_group 1). 2 CTAs/SM.   [R8 kernel + mb0]
// ---------------------------------------------------------------------------
static constexpr int PITCH  = 144;            // 128B data + 16B pad
static constexpr int TILE   = 128 * PITCH;    // 18432
static constexpr int STAGE  = 2 * TILE;       // A,B = 36864
static constexpr int NSTG   = 3;
static constexpr int OFF_A  = 0;
static constexpr int OFF_B  = TILE;
static constexpr int OFF_PART = NSTG * STAGE;         // 110592
static constexpr int OFF_H    = OFF_PART + 1024;
static constexpr int OFF_V    = OFF_H + 512;
static constexpr int SMEM_TOTAL = OFF_V + 512;        // 112640
static constexpr int NCHUNK = ENC_ / 64;              // 32
static constexpr int A_STRIDE = 128 * 64;             // halves per chunk
static constexpr int B_STRIDE = 512 * 64;

__global__ __launch_bounds__(256, 2) void score_mma_kernel(
    const float* __restrict__ V, int mb0)
{
    extern __shared__ char smem[];
    const uint32_t sb = smem_u32(smem);
    const int tid  = threadIdx.x;
    const int lane = tid & 31;
    const int wid  = tid >> 5;
    const int wm   = wid & 3;        // warp m: 4 x 32 rows
    const int wn   = wid >> 2;       // warp n: 2 x 64 cols
    const int nc   = blockIdx.x;     // n chunk (128 cols)
    const int mb   = mb0 + blockIdx.y;
    const int m0   = mb * 128;
    const int b    = mb >> 3;

    float* partS = (float*)(smem + OFF_PART);
    float* Hs    = (float*)(smem + OFF_H);
    float* Vs    = (float*)(smem + OFF_V);
    if (tid < 128) {
        Hs[tid] = g_H[b * ATT_ + nc * 128 + tid];
        Vs[tid] = V[nc * 128 + tid];
    }

    float d[2][8][4];
#pragma unroll
    for (int mt = 0; mt < 2; ++mt)
#pragma unroll
        for (int nt = 0; nt < 8; ++nt)
#pragma unroll
            for (int e = 0; e < 4; ++e) d[mt][nt][e] = 0.f;

    uint32_t dsto[4];
    const __half* pA[4];
    const __half* pB[4];
#pragma unroll
    for (int e = 0; e < 4; ++e) {
        int j = tid + e * 256, row = j >> 3, q = j & 7;
        dsto[e] = (uint32_t)(row * PITCH + q * 16);
        pA[e] = g_F16 + (((size_t)(mb * 32) * 128 + row) << 6) + q * 8;
        pB[e] = g_B16 + (((size_t)(nc * 128 + row)) << 6) + q * 8;
    }

    // ---- prologue: chunks 0,1 -> stages 0,1 ----
#pragma unroll
    for (int c = 0; c < 2; ++c) {
        const uint32_t stg = sb + c * STAGE;
#pragma unroll
        for (int e = 0; e < 4; ++e) {
            cp16(stg + OFF_A + dsto[e], pA[e]);
            cp16(stg + OFF_B + dsto[e], pB[e]);
            pA[e] += A_STRIDE;
            pB[e] += B_STRIDE;
        }
        cp_commit();
    }

    const uint32_t aoff0 = OFF_A + (uint32_t)(wm * 32 + (lane & 15)) * PITCH +
                           (uint32_t)(((lane >> 4) & 1) * 16);
    const uint32_t aoff1 = aoff0 + 16 * PITCH;
    uint32_t boff[4];
#pragma unroll
    for (int p = 0; p < 4; ++p)
        boff[p] = OFF_B + (uint32_t)(wn * 64 + p * 16 + (lane & 15)) * PITCH +
                  (uint32_t)(((lane >> 4) & 1) * 16);

    int cs = 0, ps = 2;   // compute stage, prefetch stage
#pragma unroll 1
    for (int i = 0; i < NCHUNK; ++i) {
        const uint32_t stg = sb + cs * STAGE;
        if (++cs == NSTG) cs = 0;

        cp_wait1();        // chunk i complete (newest group may still fly)
        __syncthreads();

        if (i + 2 < NCHUNK) {
            const uint32_t nstg = sb + ps * STAGE;
            if (++ps == NSTG) ps = 0;
#pragma unroll
            for (int e = 0; e < 4; ++e) {
                cp16(nstg + OFF_A + dsto[e], pA[e]);
                cp16(nstg + OFF_B + dsto[e], pB[e]);
                pA[e] += A_STRIDE;
                pB[e] += B_STRIDE;
            }
            cp_commit();
        }

        // ---- compute chunk i on stage stg: 4 k16 slabs ----
#pragma unroll
        for (int kk = 0; kk < 4; ++kk) {
            const uint32_t ko = (uint32_t)(kk * 32);
            uint32_t a0[4], a1[4];
            ldsm_x4(a0, stg + aoff0 + ko);
            ldsm_x4(a1, stg + aoff1 + ko);
            uint32_t bb[8][2];
#pragma unroll
            for (int p = 0; p < 4; ++p) {       // paired ldsm: 2 n-tiles per x4
                uint32_t r[4];
                ldsm_x4(r, stg + boff[p] + ko);
                bb[2 * p][0]     = r[0];
                bb[2 * p + 1][0] = r[1];
                bb[2 * p][1]     = r[2];
                bb[2 * p + 1][1] = r[3];
            }
#pragma unroll
            for (int nt = 0; nt < 8; ++nt) {
                mma_f16(d[0][nt], a0, bb[nt]);
                mma_f16(d[1][nt], a1, bb[nt]);
            }
        }
    }

    // ---- epilogue: tanh + V-weighted row reduction over this 128-col chunk ----
#pragma unroll
    for (int mt = 0; mt < 2; ++mt) {
        float s0 = 0.f, s1 = 0.f;
#pragma unroll
        for (int nt = 0; nt < 8; ++nt) {
            int c0 = wn * 64 + nt * 8 + (lane & 3) * 2;
            float h0 = Hs[c0], v0 = Vs[c0];
            float h1 = Hs[c0 + 1], v1 = Vs[c0 + 1];
            s0 += fast_tanh(d[mt][nt][0] + h0) * v0 + fast_tanh(d[mt][nt][1] + h1) * v1;
            s1 += fast_tanh(d[mt][nt][2] + h0) * v0 + fast_tanh(d[mt][nt][3] + h1) * v1;
        }
#pragma unroll
        for (int o = 1; o <= 2; o <<= 1) {
            s0 += __shfl_xor_sync(~0u, s0, o);
            s1 += __shfl_xor_sync(~0u, s1, o);
        }
        if ((lane & 3) == 0) {
            int r = wm * 32 + mt * 16 + (lane >> 2);
            partS[wn * 128 + r]     = s0;
            partS[wn * 128 + r + 8] = s1;
        }
    }
    __syncthreads();
    if (tid < 128)
        g_scorep[nc * BL_ + m0 + tid] = partS[tid] + partS[128 + tid];
}

// ---------------------------------------------------------------------------
// Kernel D: combine partials + softmax over L per batch
// ---------------------------------------------------------------------------
__global__ void softmax_kernel(const float* __restrict__ bv, float* __restrict__ w) {
    __shared__ float redm[32];
    __shared__ float reds[32];
    const int b = blockIdx.x, t = threadIdx.x;
    const int idx = b * L_ + t;
    float s = g_scorep[idx] + g_scorep[BL_ + idx] + g_scorep[2 * BL_ + idx] +
              g_scorep[3 * BL_ + idx] + bv[0];
    float m = s;
#pragma unroll
    for (int o = 16; o > 0; o >>= 1) m = fmaxf(m, __shfl_xor_sync(~0u, m, o));
    if ((t & 31) == 0) redm[t >> 5] = m;
    __syncthreads();
    if (t < 32) {
        float v = redm[t];
#pragma unroll
        for (int o = 16; o > 0; o >>= 1) v = fmaxf(v, __shfl_xor_sync(~0u, v, o));
        redm[t] = v;
    }
    __syncthreads();
    m = redm[0];
    const float e = expf(s - m);
    float sum = e;
#pragma unroll
    for (int o = 16; o > 0; o >>= 1) sum += __shfl_xor_sync(~0u, sum, o);
    if ((t & 31) == 0) reds[t >> 5] = sum;
    __syncthreads();
    if (t < 32) {
        float v = reds[t];
#pragma unroll
        for (int o = 16; o > 0; o >>= 1) v += __shfl_xor_sync(~0u, v, o);
        reds[t] = v;
    }
    __syncthreads();
    w[idx] = e / reds[0];
}

// ---------------------------------------------------------------------------
// Kernel E/F: context = sum_l w*F  (fp16 tiled F; 8 L-partials, then reduced)
// ---------------------------------------------------------------------------
__global__ void context_part_kernel(const float* __restrict__ w) {
    __shared__ float ws[128];
    const int b = blockIdx.y, z = blockIdx.z, t = threadIdx.x;
    ws[t] = w[b * L_ + z * 128 + t];
    __syncthreads();
    const int e0 = blockIdx.x * 512 + t * 4;
    const int mb = b * 8 + z;
    const int c  = e0 >> 6, kk = e0 & 63;
    const __half* base = g_F16 + (((size_t)(mb * 32 + c) * 128) << 6) + kk;
    float4 acc = make_float4(0.f, 0.f, 0.f, 0.f);
#pragma unroll 4
    for (int l = 0; l < 128; ++l) {
        uint2 v = *(const uint2*)(base + ((size_t)l << 6));
        float2 f01 = __half22float2(*(const __half2*)&v.x);
        float2 f23 = __half22float2(*(const __half2*)&v.y);
        const float wl = ws[l];
        acc.x += wl * f01.x; acc.y += wl * f01.y;
        acc.z += wl * f23.x; acc.w += wl * f23.y;
    }
    *(float4*)&g_ctxp[(size_t)(z * B_ + b) * ENC_ + e0] = acc;
}

__global__ void context_reduce_kernel(float* __restrict__ ctx) {
    const int i = (blockIdx.x * 256 + threadIdx.x) * 4;
    float4 acc = make_float4(0.f, 0.f, 0.f, 0.f);
#pragma unroll
    for (int p = 0; p < 8; ++p) {
        float4 a = *(const float4*)&g_ctxp[(size_t)p * B_ * ENC_ + i];
        acc.x += a.x; acc.y += a.y; acc.z += a.z; acc.w += a.w;
    }
    *(float4*)&ctx[i] = acc;
}

// ---------------------------------------------------------------------------
// Launch: prep_F quarters on a forked stream overlap score of earlier quarters
// ---------------------------------------------------------------------------
extern "C" void kernel_launch(void* const* d_in, const int* in_sizes, int n_in,
                              void* d_out, int out_size) {
    const float* F   = (const float*)d_in[0];
    const float* hid = (const float*)d_in[1];
    const float* W1  = (const float*)d_in[2];
    const float* b1  = (const float*)d_in[3];
    const float* W2  = (const float*)d_in[4];
    const float* b2  = (const float*)d_in[5];
    const float* V   = (const float*)d_in[6];
    const float* bv  = (const float*)d_in[7];

    float* out = (float*)d_out;
    float* ctx = out;
    float* wts = out + B_ * ENC_;

    // one-time host objects (created on the first, non-captured, call)
    static cudaStream_t s2 = nullptr;
    static cudaEvent_t eFork, eQ1, eQ2, eQ3;
    if (s2 == nullptr) {
        cudaStreamCreateWithFlags(&s2, cudaStreamNonBlocking);
        cudaEventCreateWithFlags(&eFork, cudaEventDisableTiming);
        cudaEventCreateWithFlags(&eQ1, cudaEventDisableTiming);
        cudaEventCreateWithFlags(&eQ2, cudaEventDisableTiming);
        cudaEventCreateWithFlags(&eQ3, cudaEventDisableTiming);
        cudaFuncSetAttribute(score_mma_kernel,
                             cudaFuncAttributeMaxDynamicSharedMemorySize, SMEM_TOTAL);
    }

    const int QMB   = 128;                               // mb per quarter
    const int QPREP = (QMB * 128 * (ENC_ / 4)) / 256;    // prep blocks per quarter

    // fork s2 off the capture (default) stream
    cudaEventRecord(eFork, 0);
    cudaStreamWaitEvent(s2, eFork, 0);

    // branch A (default stream): small kernels + quarter 0 prep
    proj_h_kernel<<<B_, ATT_>>>(hid, W2, b2, b1);
    prep_B_kernel<<<(ENC_ * ATT_) / 256, 256>>>(W1);
    prep_F_kernel<<<QPREP, 256>>>(F, 0);

    // branch B (s2): quarters 1..3 prep, each signaling completion
    prep_F_kernel<<<QPREP, 256, 0, s2>>>(F, QMB);
    cudaEventRecord(eQ1, s2);
    prep_F_kernel<<<QPREP, 256, 0, s2>>>(F, 2 * QMB);
    cudaEventRecord(eQ2, s2);
    prep_F_kernel<<<QPREP, 256, 0, s2>>>(F, 3 * QMB);
    cudaEventRecord(eQ3, s2);

    // score quarters on default stream; q>=1 waits its prep (runs under q-1's score)
    score_mma_kernel<<<dim3(4, QMB), 256, SMEM_TOTAL>>>(V, 0);
    cudaStreamWaitEvent(0, eQ1, 0);
    score_mma_kernel<<<dim3(4, QMB), 256, SMEM_TOTAL>>>(V, QMB);
    cudaStreamWaitEvent(0, eQ2, 0);
    score_mma_kernel<<<dim3(4, QMB), 256, SMEM_TOTAL>>>(V, 2 * QMB);
    cudaStreamWaitEvent(0, eQ3, 0);
    score_mma_kernel<<<dim3(4, QMB), 256, SMEM_TOTAL>>>(V, 3 * QMB);

    softmax_kernel<<<B_, L_>>>(bv, wts);
    context_part_kernel<<<dim3(ENC_ / 512, B_, 8), 128>>>(wts);
    context_reduce_kernel<<<(B_ * ENC_) / 1024, 256>>>(ctx);
}

// round 15
// speedup vs baseline: 1.2368x; 1.2112x over previous
#include <cuda_runtime.h>
#include <cuda_fp16.h>
#include <math.h>
#include <stdint.h>

#define B_   64
#define L_   1024
#define ENC_ 2048
#define DEC_ 512
#define ATT_ 512
#define BL_  (B_ * L_)

// ---------------------------------------------------------------------------
// Device scratch
// ---------------------------------------------------------------------------
__device__ float g_H[B_ * ATT_];                          // proj_h + b2 + b1
// W1 fp16, layout [c=k/64][n 512][k 64]
__device__ __align__(128) __half g_B16[ENC_ * ATT_];
// F fp16, layout [mb][c][row 128][k 64] — written by score (ncp==0 CTAs)
__device__ __align__(128) __half g_F16[(size_t)BL_ * ENC_];
__device__ float g_scorep[2 * BL_];                       // per-N-half score partials
__device__ float g_ctxp[8 * B_ * ENC_];                   // context partials

// ---------------------------------------------------------------------------
// Helpers
// ---------------------------------------------------------------------------
__device__ __forceinline__ uint32_t smem_u32(const void* p) {
    uint32_t a;
    asm("{ .reg .u64 t; cvta.to.shared.u64 t, %1; cvt.u32.u64 %0, t; }" : "=r"(a) : "l"(p));
    return a;
}
__device__ __forceinline__ void cp16(uint32_t dst, const void* src) {
    asm volatile("cp.async.cg.shared.global [%0], [%1], 16;" :: "r"(dst), "l"(src));
}
__device__ __forceinline__ void cp_commit() {
    asm volatile("cp.async.commit_group;" ::: "memory");
}
__device__ __forceinline__ void cp_wait0() {
    asm volatile("cp.async.wait_group 0;" ::: "memory");
}
__device__ __forceinline__ void ldsm_x4(uint32_t* r, uint32_t addr) {
    asm volatile("ldmatrix.sync.aligned.m8n8.x4.shared.b16 {%0,%1,%2,%3}, [%4];"
                 : "=r"(r[0]), "=r"(r[1]), "=r"(r[2]), "=r"(r[3]) : "r"(addr));
}
__device__ __forceinline__ void mma_f16(float* d, const uint32_t* a, const uint32_t* b) {
    asm volatile(
        "mma.sync.aligned.m16n8k16.row.col.f32.f16.f16.f32 "
        "{%0,%1,%2,%3}, {%4,%5,%6,%7}, {%8,%9}, {%0,%1,%2,%3};"
        : "+f"(d[0]), "+f"(d[1]), "+f"(d[2]), "+f"(d[3])
        : "r"(a[0]), "r"(a[1]), "r"(a[2]), "r"(a[3]), "r"(b[0]), "r"(b[1]));
}
__device__ __forceinline__ float fast_tanh(float x) {
    float e = __expf(2.f * x);
    return __fdividef(e - 1.f, e + 1.f);
}

// ---------------------------------------------------------------------------
// Kernel A: H = hidden @ W2 + b2 + b1
// ---------------------------------------------------------------------------
__global__ void proj_h_kernel(const float* __restrict__ hidden,
                              const float* __restrict__ W2,
                              const float* __restrict__ b2,
                              const float* __restrict__ b1) {
    __shared__ float hs[DEC_];
    int b = blockIdx.x, a = threadIdx.x;
    hs[a] = hidden[b * DEC_ + a];
    __syncthreads();
    float acc = 0.f;
#pragma unroll 8
    for (int d = 0; d < DEC_; ++d) acc += hs[d] * W2[d * ATT_ + a];
    g_H[b * ATT_ + a] = acc + b2[a] + b1[a];
}

// ---------------------------------------------------------------------------
// Kernel B: W1 [ENC, ATT] fp32 -> fp16, layout [c=k/64][n][k64]
// ---------------------------------------------------------------------------
__global__ void prep_B_kernel(const float* __restrict__ W1) {
    int idx = blockIdx.x * 256 + threadIdx.x;   // idx = k*512 + n
    if (idx >= ENC_ * ATT_) return;
    int k = idx >> 9, n = idx & 511;
    int c = k >> 6, kk = k & 63;
    g_B16[((size_t)(c * 512 + n) << 6) + kk] = __float2half_rn(W1[idx]);
}

// ---------------------------------------------------------------------------
// Kernel C: fused fp16 GEMM + in-kernel A conversion + tanh + V-reduction
// Grid: (2 ncp, 512 mb), ncp fastest (pair shares F via L2).
// CTA: 128x256 tile, 512 thr (4wm x 4wn, warp tile 32x64), KC=64, 2 stages.
// A: fp32 LDG->cvt->STS (conversion amortized over 256 cols); ncp==0 CTA
//    also STGs fp16 tiles to g_F16 for the context kernel. No prep_F.
// B: fp16 cp.async + paired ldsm.
// ---------------------------------------------------------------------------
static constexpr int PITCH   = 144;              // 128B data + 16B pad
static constexpr int A_TILE  = 128 * PITCH;      // 18432
static constexpr int B_TILE  = 256 * PITCH;      // 36864
static constexpr int STAGE   = A_TILE + B_TILE;  // 55296
static constexpr int OFF_A   = 0;
static constexpr int OFF_B   = A_TILE;
static constexpr int OFF_PART = 2 * STAGE;            // 110592: 4*128 floats
static constexpr int OFF_H    = OFF_PART + 2048;
static constexpr int OFF_V    = OFF_H + 1024;
static constexpr int SMEM_TOTAL = OFF_V + 1024;       // 114688
static constexpr int NCHUNK  = ENC_ / 64;             // 32

__global__ __launch_bounds__(512, 1) void score_mma_kernel(
    const float* __restrict__ F, const float* __restrict__ V)
{
    extern __shared__ char smem[];
    const uint32_t sb = smem_u32(smem);
    const int tid  = threadIdx.x;
    const int lane = tid & 31;
    const int wid  = tid >> 5;
    const int wm   = wid & 3;        // warp m: 4 x 32 rows
    const int wn   = wid >> 2;       // warp n: 4 x 64 cols
    const int ncp  = blockIdx.x;     // n half (256 cols)
    const int mb   = blockIdx.y;
    const int m0   = mb * 128;
    const int b    = mb >> 3;

    float* partS = (float*)(smem + OFF_PART);
    float* Hs    = (float*)(smem + OFF_H);
    float* Vs    = (float*)(smem + OFF_V);
    if (tid < 256) {
        Hs[tid] = g_H[b * ATT_ + ncp * 256 + tid];
        Vs[tid] = V[ncp * 256 + tid];
    }

    float d[2][8][4];
#pragma unroll
    for (int mt = 0; mt < 2; ++mt)
#pragma unroll
        for (int nt = 0; nt < 8; ++nt)
#pragma unroll
            for (int e = 0; e < 4; ++e) d[mt][nt][e] = 0.f;

    // A: 128x64 fp32 per chunk = 2048 float4 / 512 thr = 4/thread
    // v = tid + t*512; row = v>>4; q = v&15 (float4 within row)
    const char* pFb = (const char*)(F + (size_t)m0 * ENC_);   // +256B per chunk
    char*       pOb = (char*)(g_F16 + ((size_t)mb * 32 * 128 << 6)); // +16384B per chunk
    uint32_t aSrc[4], aDst[4], oOff[4];
#pragma unroll
    for (int t = 0; t < 4; ++t) {
        int v = tid + t * 512, row = v >> 4, q = v & 15;
        aSrc[t] = (uint32_t)(row * (ENC_ * 4) + q * 16);
        aDst[t] = (uint32_t)(OFF_A + row * PITCH + q * 8);
        oOff[t] = (uint32_t)((row * 64 + q * 4) * 2);
    }
    // B: 256 rows x 128B per chunk = 2048 x16B / 512 thr = 4/thread
    const char* pBb = (const char*)(g_B16 + ((size_t)(ncp * 256) << 6)); // +65536B per chunk
    uint32_t bSrc[4], bDst[4];
#pragma unroll
    for (int e = 0; e < 4; ++e) {
        int j = tid + e * 512, row = j >> 3, q = j & 7;
        bSrc[e] = (uint32_t)((row * 64 + q * 8) * 2);
        bDst[e] = (uint32_t)(OFF_B + row * PITCH + q * 16);
    }

    // ---- prologue: chunk 0 -> stage 0 ----
    float4 fr[4];
#pragma unroll
    for (int t = 0; t < 4; ++t) fr[t] = *(const float4*)(pFb + aSrc[t]);
#pragma unroll
    for (int e = 0; e < 4; ++e) cp16(sb + bDst[e], pBb + bSrc[e]);
    cp_commit();
#pragma unroll
    for (int t = 0; t < 4; ++t) {
        __half2 h01 = __floats2half2_rn(fr[t].x, fr[t].y);
        __half2 h23 = __floats2half2_rn(fr[t].z, fr[t].w);
        uint2 v = make_uint2(*(uint32_t*)&h01, *(uint32_t*)&h23);
        *(uint2*)(smem + aDst[t]) = v;
        if (ncp == 0) *(uint2*)(pOb + oOff[t]) = v;
    }
    pFb += 256;  pBb += 65536;  pOb += 16384;

    // ldsm base offsets (stage-relative)
    const uint32_t aoff0 = OFF_A + (uint32_t)(wm * 32 + (lane & 15)) * PITCH +
                           (uint32_t)(((lane >> 4) & 1) * 16);
    const uint32_t aoff1 = aoff0 + 16 * PITCH;
    uint32_t boff[4];
#pragma unroll
    for (int p = 0; p < 4; ++p)
        boff[p] = OFF_B + (uint32_t)(wn * 64 + p * 16 + (lane & 15)) * PITCH +
                  (uint32_t)(((lane >> 4) & 1) * 16);

#pragma unroll 1
    for (int i = 0; i < NCHUNK; ++i) {
        const int s = i & 1;
        const uint32_t stg = sb + s * STAGE;

        // prefetch A(i+1) fp32 into regs (overlaps wait + compute)
        if (i + 1 < NCHUNK) {
#pragma unroll
            for (int t = 0; t < 4; ++t) fr[t] = *(const float4*)(pFb + aSrc[t]);
        }

        cp_wait0();
        __syncthreads();   // stage s populated; all warps done reading s^1

        if (i + 1 < NCHUNK) {
            const uint32_t nstg = sb + (s ^ 1) * STAGE;
#pragma unroll
            for (int e = 0; e < 4; ++e) cp16(nstg + bDst[e], pBb + bSrc[e]);
            cp_commit();
#pragma unroll
            for (int t = 0; t < 4; ++t) {
                __half2 h01 = __floats2half2_rn(fr[t].x, fr[t].y);
                __half2 h23 = __floats2half2_rn(fr[t].z, fr[t].w);
                uint2 v = make_uint2(*(uint32_t*)&h01, *(uint32_t*)&h23);
                *(uint2*)((char*)smem + (s ^ 1) * STAGE + aDst[t]) = v;
                if (ncp == 0) *(uint2*)(pOb + oOff[t]) = v;
            }
            pFb += 256;  pBb += 65536;  pOb += 16384;
        }

        // ---- compute chunk i on stage s: 4 k16 slabs ----
#pragma unroll
        for (int kk = 0; kk < 4; ++kk) {
            const uint32_t ko = (uint32_t)(kk * 32);
            uint32_t a0[4], a1[4];
            ldsm_x4(a0, stg + aoff0 + ko);
            ldsm_x4(a1, stg + aoff1 + ko);
            uint32_t bb[8][2];
#pragma unroll
            for (int p = 0; p < 4; ++p) {       // paired ldsm: 2 n-tiles per x4
                uint32_t r[4];
                ldsm_x4(r, stg + boff[p] + ko);
                bb[2 * p][0]     = r[0];
                bb[2 * p + 1][0] = r[1];
                bb[2 * p][1]     = r[2];
                bb[2 * p + 1][1] = r[3];
            }
#pragma unroll
            for (int nt = 0; nt < 8; ++nt) {
                mma_f16(d[0][nt], a0, bb[nt]);
                mma_f16(d[1][nt], a1, bb[nt]);
            }
        }
    }

    // ---- epilogue: tanh + V-weighted row reduction over this 256-col half ----
#pragma unroll
    for (int mt = 0; mt < 2; ++mt) {
        float s0 = 0.f, s1 = 0.f;
#pragma unroll
        for (int nt = 0; nt < 8; ++nt) {
            int c0 = wn * 64 + nt * 8 + (lane & 3) * 2;
            float h0 = Hs[c0], v0 = Vs[c0];
            float h1 = Hs[c0 + 1], v1 = Vs[c0 + 1];
            s0 += fast_tanh(d[mt][nt][0] + h0) * v0 + fast_tanh(d[mt][nt][1] + h1) * v1;
            s1 += fast_tanh(d[mt][nt][2] + h0) * v0 + fast_tanh(d[mt][nt][3] + h1) * v1;
        }
#pragma unroll
        for (int o = 1; o <= 2; o <<= 1) {
            s0 += __shfl_xor_sync(~0u, s0, o);
            s1 += __shfl_xor_sync(~0u, s1, o);
        }
        if ((lane & 3) == 0) {
            int r = wm * 32 + mt * 16 + (lane >> 2);
            partS[wn * 128 + r]     = s0;
            partS[wn * 128 + r + 8] = s1;
        }
    }
    __syncthreads();
    if (tid < 128)
        g_scorep[ncp * BL_ + m0 + tid] = partS[tid] + partS[128 + tid] +
                                         partS[256 + tid] + partS[384 + tid];
}

// ---------------------------------------------------------------------------
// Kernel D: combine partials + softmax over L per batch
// ---------------------------------------------------------------------------
__global__ void softmax_kernel(const float* __restrict__ bv, float* __restrict__ w) {
    __shared__ float redm[32];
    __shared__ float reds[32];
    const int b = blockIdx.x, t = threadIdx.x;
    const int idx = b * L_ + t;
    float s = g_scorep[idx] + g_scorep[BL_ + idx] + bv[0];
    float m = s;
#pragma unroll
    for (int o = 16; o > 0; o >>= 1) m = fmaxf(m, __shfl_xor_sync(~0u, m, o));
    if ((t & 31) == 0) redm[t >> 5] = m;
    __syncthreads();
    if (t < 32) {
        float v = redm[t];
#pragma unroll
        for (int o = 16; o > 0; o >>= 1) v = fmaxf(v, __shfl_xor_sync(~0u, v, o));
        redm[t] = v;
    }
    __syncthreads();
    m = redm[0];
    const float e = expf(s - m);
    float sum = e;
#pragma unroll
    for (int o = 16; o > 0; o >>= 1) sum += __shfl_xor_sync(~0u, sum, o);
    if ((t & 31) == 0) reds[t >> 5] = sum;
    __syncthreads();
    if (t < 32) {
        float v = reds[t];
#pragma unroll
        for (int o = 16; o > 0; o >>= 1) v += __shfl_xor_sync(~0u, v, o);
        reds[t] = v;
    }
    __syncthreads();
    w[idx] = e / reds[0];
}

// ---------------------------------------------------------------------------
// Kernel E/F: context = sum_l w*F  (fp16 tiles from score; 8 L-partials)
// ---------------------------------------------------------------------------
__global__ void context_part_kernel(const float* __restrict__ w) {
    __shared__ float ws[128];
    const int b = blockIdx.y, z = blockIdx.z, t = threadIdx.x;
    ws[t] = w[b * L_ + z * 128 + t];
    __syncthreads();
    const int e0 = blockIdx.x * 512 + t * 4;
    const int mb = b * 8 + z;
    const int c  = e0 >> 6, kk = e0 & 63;
    const __half* base = g_F16 + (((size_t)(mb * 32 + c) * 128) << 6) + kk;
    float4 acc = make_float4(0.f, 0.f, 0.f, 0.f);
#pragma unroll 4
    for (int l = 0; l < 128; ++l) {
        uint2 v = *(const uint2*)(base + ((size_t)l << 6));
        float2 f01 = __half22float2(*(const __half2*)&v.x);
        float2 f23 = __half22float2(*(const __half2*)&v.y);
        const float wl = ws[l];
        acc.x += wl * f01.x; acc.y += wl * f01.y;
        acc.z += wl * f23.x; acc.w += wl * f23.y;
    }
    *(float4*)&g_ctxp[(size_t)(z * B_ + b) * ENC_ + e0] = acc;
}

__global__ void context_reduce_kernel(float* __restrict__ ctx) {
    const int i = (blockIdx.x * 256 + threadIdx.x) * 4;
    float4 acc = make_float4(0.f, 0.f, 0.f, 0.f);
#pragma unroll
    for (int p = 0; p < 8; ++p) {
        float4 a = *(const float4*)&g_ctxp[(size_t)p * B_ * ENC_ + i];
        acc.x += a.x; acc.y += a.y; acc.z += a.z; acc.w += a.w;
    }
    *(float4*)&ctx[i] = acc;
}

// ---------------------------------------------------------------------------
// Launch
// ---------------------------------------------------------------------------
extern "C" void kernel_launch(void* const* d_in, const int* in_sizes, int n_in,
                              void* d_out, int out_size) {
    const float* F   = (const float*)d_in[0];
    const float* hid = (const float*)d_in[1];
    const float* W1  = (const float*)d_in[2];
    const float* b1  = (const float*)d_in[3];
    const float* W2  = (const float*)d_in[4];
    const float* b2  = (const float*)d_in[5];
    const float* V   = (const float*)d_in[6];
    const float* bv  = (const float*)d_in[7];

    float* out = (float*)d_out;
    float* ctx = out;
    float* wts = out + B_ * ENC_;

    cudaFuncSetAttribute(score_mma_kernel,
                         cudaFuncAttributeMaxDynamicSharedMemorySize, SMEM_TOTAL);

    proj_h_kernel<<<B_, ATT_>>>(hid, W2, b2, b1);
    prep_B_kernel<<<(ENC_ * ATT_) / 256, 256>>>(W1);
    score_mma_kernel<<<dim3(2, BL_ / 128), 512, SMEM_TOTAL>>>(F, V);
    softmax_kernel<<<B_, L_>>>(bv, wts);
    context_part_kernel<<<dim3(ENC_ / 512, B_, 8), 128>>>(wts);
    context_reduce_kernel<<<(B_ * ENC_) / 1024, 256>>>(ctx);
}